// round 4
// baseline (speedup 1.0000x reference)
#include <cuda_runtime.h>

#define N_ROWS 8192
#define DIM    128
#define NCLS   64
#define NT     64          // number of 128-wide j tiles (8192/128)
#define TILE   128
#define SPAD   129         // padded smem row stride (floats)

// Scratch (no cudaMalloc allowed): ~12 MB of __device__ globals.
__device__ float g_xn[N_ROWS * DIM];        // normalized rows
__device__ float g_negp[NT * N_ROWS];       // per-(jtile,row) partial neg sums
__device__ float g_posp[NT * N_ROWS];       // per-(jtile,row) partial pos sums
__device__ int   g_cnt[NCLS];               // label histogram
__device__ float g_bsum[64];                // per-block loss partials

// exp(dot / 0.5) = 2^(dot * log2(e)/0.5), FMA-pipe only (no MUFU).
// dot in [-1,1] -> t in [-2.886, 2.886]. Degree-7 Taylor of 2^f on [0,1),
// rel err ~1e-6.
__device__ __forceinline__ float exp_sim(float dot) {
    float t  = dot * 2.8853900817779268f;
    float fl = floorf(t);
    float f  = t - fl;
    float p  = 1.52527338e-5f;
    p = fmaf(p, f, 1.54035304e-4f);
    p = fmaf(p, f, 1.33335581e-3f);
    p = fmaf(p, f, 9.61812911e-3f);
    p = fmaf(p, f, 5.55041087e-2f);
    p = fmaf(p, f, 2.40226507e-1f);
    p = fmaf(p, f, 6.93147181e-1f);
    p = fmaf(p, f, 1.0f);
    int e = (int)fl;
    return p * __int_as_float((e + 127) << 23);
}

__global__ void k_init() {
    if (threadIdx.x < NCLS) g_cnt[threadIdx.x] = 0;
}

// One block per row: L2-normalize + label histogram.
__global__ void k_norm(const float* __restrict__ x,
                       const int* __restrict__ lab) {
    int row = blockIdx.x;
    int t   = threadIdx.x;
    float v = x[row * DIM + t];
    float ss = v * v;
    #pragma unroll
    for (int o = 16; o > 0; o >>= 1)
        ss += __shfl_xor_sync(0xffffffffu, ss, o);
    __shared__ float ws[4];
    if ((t & 31) == 0) ws[t >> 5] = ss;
    __syncthreads();
    float tot = ws[0] + ws[1] + ws[2] + ws[3];
    float nrm = fmaxf(sqrtf(tot), 1e-12f);
    g_xn[row * DIM + t] = v / nrm;
    if (t == 0) atomicAdd(&g_cnt[lab[row] & (NCLS - 1)], 1);
}

// 128x128 tile Gram + exp + masked row-partials.
// Thread (tx,ty): tx=tid&15, ty=tid>>4. Micro-tile i = ty+16m, j = tx+16n
// (strided -> conflict-free k-major LDS reads).
__global__ void __launch_bounds__(256, 1)
k_pair(const int* __restrict__ lab) {
    extern __shared__ float sm[];
    float* As  = sm;                    // [128][SPAD], k-major: As[k*SPAD + i]
    float* Bs  = sm + TILE * SPAD;      // [128][SPAD]
    int*   labI = (int*)(Bs + TILE * SPAD);
    int*   labJ = labI + TILE;

    int tid = threadIdx.x;
    int tx  = tid & 15;
    int ty  = tid >> 4;
    int i0  = blockIdx.y * TILE;
    int j0  = blockIdx.x * TILE;

    // Load both tiles (coalesced LDG, transposed STS, 4-way conflict max).
    #pragma unroll
    for (int it = 0; it < 16; it++) {
        int idx = tid + it * 256;       // 0..4095
        int kq  = idx & 31;             // float4 column
        int r   = idx >> 5;             // row within tile
        float4 va = *(const float4*)&g_xn[(size_t)(i0 + r) * DIM + kq * 4];
        As[(4 * kq + 0) * SPAD + r] = va.x;
        As[(4 * kq + 1) * SPAD + r] = va.y;
        As[(4 * kq + 2) * SPAD + r] = va.z;
        As[(4 * kq + 3) * SPAD + r] = va.w;
        float4 vb = *(const float4*)&g_xn[(size_t)(j0 + r) * DIM + kq * 4];
        Bs[(4 * kq + 0) * SPAD + r] = vb.x;
        Bs[(4 * kq + 1) * SPAD + r] = vb.y;
        Bs[(4 * kq + 2) * SPAD + r] = vb.z;
        Bs[(4 * kq + 3) * SPAD + r] = vb.w;
    }
    if (tid < TILE) {
        labI[tid] = lab[i0 + tid];
        labJ[tid] = lab[j0 + tid];
    }
    __syncthreads();

    float acc[8][8];
    #pragma unroll
    for (int m = 0; m < 8; m++)
        #pragma unroll
        for (int n = 0; n < 8; n++) acc[m][n] = 0.0f;

    #pragma unroll 4
    for (int k = 0; k < DIM; k++) {
        float a[8], b[8];
        #pragma unroll
        for (int m = 0; m < 8; m++) a[m] = As[k * SPAD + ty + 16 * m];
        #pragma unroll
        for (int n = 0; n < 8; n++) b[n] = Bs[k * SPAD + tx + 16 * n];
        #pragma unroll
        for (int m = 0; m < 8; m++)
            #pragma unroll
            for (int n = 0; n < 8; n++)
                acc[m][n] = fmaf(a[m], b[n], acc[m][n]);
    }

    int li[8], lj[8];
    #pragma unroll
    for (int m = 0; m < 8; m++) li[m] = labI[ty + 16 * m];
    #pragma unroll
    for (int n = 0; n < 8; n++) lj[n] = labJ[tx + 16 * n];

    // Per-row exp + mask, then reduce across the 16 tx lanes (lane%16 == tx).
    #pragma unroll
    for (int m = 0; m < 8; m++) {
        float neg = 0.0f, pos = 0.0f;
        #pragma unroll
        for (int n = 0; n < 8; n++) {
            float s = exp_sim(acc[m][n]);
            neg += s;
            pos += (li[m] == lj[n]) ? s : 0.0f;
        }
        #pragma unroll
        for (int o = 1; o < 16; o <<= 1) {
            neg += __shfl_xor_sync(0xffffffffu, neg, o);
            pos += __shfl_xor_sync(0xffffffffu, pos, o);
        }
        if (tx == 0) {
            int row = i0 + ty + 16 * m;
            g_negp[(size_t)blockIdx.x * N_ROWS + row] = neg;
            g_posp[(size_t)blockIdx.x * N_ROWS + row] = pos;
        }
    }
}

// Per-row loss; partials include the diagonal -> subtract self = exp(1/T).
// (dot_ii differs from 1 by ~1e-7 fp noise; induced error on the loss ~1e-10.)
__global__ void k_row(const int* __restrict__ lab) {
    int row = blockIdx.x * 128 + threadIdx.x;
    float neg = 0.0f, pos = 0.0f;
    #pragma unroll
    for (int jt = 0; jt < NT; jt++) {
        neg += g_negp[jt * N_ROWS + row];
        pos += g_posp[jt * N_ROWS + row];
    }
    float self = exp_sim(1.0f);
    int   cnt  = g_cnt[lab[row] & (NCLS - 1)] - 1;
    float l = logf(neg - self) - logf((pos - self) / (float)cnt);

    #pragma unroll
    for (int o = 16; o > 0; o >>= 1)
        l += __shfl_xor_sync(0xffffffffu, l, o);
    __shared__ float ws[4];
    if ((threadIdx.x & 31) == 0) ws[threadIdx.x >> 5] = l;
    __syncthreads();
    if (threadIdx.x == 0)
        g_bsum[blockIdx.x] = ws[0] + ws[1] + ws[2] + ws[3];
}

__global__ void k_fin(float* __restrict__ out) {
    int t = threadIdx.x;          // 64 threads
    float v = g_bsum[t];
    #pragma unroll
    for (int o = 16; o > 0; o >>= 1)
        v += __shfl_xor_sync(0xffffffffu, v, o);
    __shared__ float s2[2];
    if ((t & 31) == 0) s2[t >> 5] = v;
    __syncthreads();
    if (t == 0) out[0] = (s2[0] + s2[1]) / (float)N_ROWS;
}

extern "C" void kernel_launch(void* const* d_in, const int* in_sizes, int n_in,
                              void* d_out, int out_size) {
    // Select inputs by element count (features: 8192*128, labels: 8192) —
    // robust to metadata ordering.
    const float* x   = (const float*)d_in[0];
    const int*   lab = (const int*)d_in[1];
    if (n_in >= 2 && in_sizes[0] < in_sizes[1]) {
        x   = (const float*)d_in[1];
        lab = (const int*)d_in[0];
    }
    float* out = (float*)d_out;

    size_t smem = (size_t)2 * TILE * SPAD * sizeof(float) + 2 * TILE * sizeof(int);
    cudaFuncSetAttribute(k_pair, cudaFuncAttributeMaxDynamicSharedMemorySize, (int)smem);

    k_init<<<1, 64>>>();
    k_norm<<<N_ROWS, 128>>>(x, lab);
    dim3 grid(NT, N_ROWS / TILE);
    k_pair<<<grid, 256, smem>>>(lab);
    k_row<<<N_ROWS / 128, 128>>>(lab);
    k_fin<<<1, 64>>>(out);
}

// round 8
// speedup vs baseline: 3.8889x; 3.8889x over previous
#include <cuda_runtime.h>
#include <cuda_bf16.h>
#include <cstdint>

#define N_ROWS 8192
#define DIM    128
#define NCLS   64
#define TI     128                 // CTA tile (M = N = 128)
#define NBI    (N_ROWS / TI)       // 64
#define NT     (NBI * 2)           // 128 partial slots per row (2 warp n-halves)
#define SROW   136                 // padded smem row stride (bf16 elems) = 272 B

// ---- scratch (__device__ globals; no cudaMalloc allowed) ----
__device__ __nv_bfloat16 g_xb[N_ROWS * DIM];   // normalized rows, bf16
__device__ float g_negp[(size_t)NT * N_ROWS];
__device__ float g_posp[(size_t)NT * N_ROWS];
__device__ int   g_cnt[NCLS];
__device__ float g_bsum[64];

#define EXSCALE 2.8853900817779268f   // log2(e)/T, T=0.5

__device__ __forceinline__ uint32_t smem_u32(const void* p) {
    uint32_t a;
    asm("{ .reg .u64 t; cvta.to.shared.u64 t, %1; cvt.u32.u64 %0, t; }" : "=r"(a) : "l"(p));
    return a;
}
__device__ __forceinline__ float ex2f(float x) {
    float r; asm("ex2.approx.f32 %0, %1;" : "=f"(r) : "f"(x)); return r;
}
__device__ __forceinline__ void ldsm4(uint32_t* r, uint32_t addr) {
    asm volatile("ldmatrix.sync.aligned.m8n8.x4.shared.b16 {%0,%1,%2,%3}, [%4];"
                 : "=r"(r[0]), "=r"(r[1]), "=r"(r[2]), "=r"(r[3]) : "r"(addr));
}
__device__ __forceinline__ void mma16816(float* d, const uint32_t* a,
                                         uint32_t b0, uint32_t b1) {
    asm volatile(
        "mma.sync.aligned.m16n8k16.row.col.f32.bf16.bf16.f32 "
        "{%0,%1,%2,%3}, {%4,%5,%6,%7}, {%8,%9}, {%0,%1,%2,%3};"
        : "+f"(d[0]), "+f"(d[1]), "+f"(d[2]), "+f"(d[3])
        : "r"(a[0]), "r"(a[1]), "r"(a[2]), "r"(a[3]), "r"(b0), "r"(b1));
}

__global__ void k_init() {
    if (threadIdx.x < NCLS) g_cnt[threadIdx.x] = 0;
}

__global__ void k_norm(const float* __restrict__ x,
                       const int* __restrict__ lab) {
    int row = blockIdx.x, t = threadIdx.x;
    float v = x[row * DIM + t];
    float ss = v * v;
    #pragma unroll
    for (int o = 16; o > 0; o >>= 1) ss += __shfl_xor_sync(0xffffffffu, ss, o);
    __shared__ float ws[4];
    if ((t & 31) == 0) ws[t >> 5] = ss;
    __syncthreads();
    float nrm = fmaxf(sqrtf(ws[0] + ws[1] + ws[2] + ws[3]), 1e-12f);
    g_xb[row * DIM + t] = __float2bfloat16(v / nrm);
    if (t == 0) atomicAdd(&g_cnt[lab[row] & (NCLS - 1)], 1);
}

// 128x128 Gram tile via ldmatrix + mma.sync (bf16 in, fp32 acc),
// fused exp + label-mask epilogue, deterministic partial writes.
__global__ void __launch_bounds__(256, 2)
k_pair(const int* __restrict__ lab) {
    extern __shared__ char sm[];
    __nv_bfloat16* As = (__nv_bfloat16*)sm;            // [128][SROW]
    __nv_bfloat16* Bs = As + TI * SROW;                // [128][SROW]
    int* labJ = (int*)(Bs + TI * SROW);                // [128]

    int tid  = threadIdx.x;
    int w    = tid >> 5;
    int lane = tid & 31;
    int i0   = blockIdx.y * TI;
    int j0   = blockIdx.x * TI;

    // Cooperative tile load: 16B chunks, coalesced LDG, padded-row STS.
    #pragma unroll
    for (int it = 0; it < 16; it++) {
        int idx = tid + it * 256;           // 0..4095
        int sub = idx >> 11;                // 0 = A, 1 = B
        int loc = idx & 2047;
        int row = loc >> 4, c = loc & 15;
        int grow = (sub ? j0 : i0) + row;
        uint4 v = *(const uint4*)((const char*)g_xb + ((size_t)grow * DIM + c * 8) * 2);
        __nv_bfloat16* dst = sub ? Bs : As;
        *(uint4*)((char*)dst + row * (SROW * 2) + c * 16) = v;
    }
    if (tid < TI) labJ[tid] = lab[j0 + tid];
    __syncthreads();

    int warp_m = w >> 1;                    // 0..3  -> 32-row slab
    int warp_n = w & 1;                     // 0..1  -> 64-col half
    uint32_t asb = smem_u32(As), bsb = smem_u32(Bs);

    // ldmatrix lane addressing (non-trans for both A and B fragments):
    // A x4: matrices (m0-7,k0-7),(m8-15,k0-7),(m0-7,k8-15),(m8-15,k8-15)
    uint32_t a_row = (uint32_t)(warp_m * 32 + (lane & 7) + ((lane >> 3) & 1) * 8);
    uint32_t a_k   = (uint32_t)((lane >> 4) * 8);
    uint32_t aaddr = asb + a_row * (SROW * 2) + a_k * 2;
    // B x4 (pair of n-frags): (n0-7,k0-7),(n0-7,k8-15),(n8-15,k0-7),(n8-15,k8-15)
    uint32_t b_n = (uint32_t)(warp_n * 64 + ((lane >> 4) << 3) + (lane & 7));
    uint32_t b_k = (uint32_t)(((lane >> 3) & 1) * 8);
    uint32_t baddr = bsb + b_n * (SROW * 2) + b_k * 2;

    float acc[2][8][4];
    #pragma unroll
    for (int mf = 0; mf < 2; mf++)
        #pragma unroll
        for (int nf = 0; nf < 8; nf++)
            #pragma unroll
            for (int e = 0; e < 4; e++) acc[mf][nf][e] = 0.0f;

    #pragma unroll
    for (int ks = 0; ks < 8; ks++) {
        uint32_t a[2][4], b[4][4];
        ldsm4(a[0], aaddr + ks * 32);
        ldsm4(a[1], aaddr + 16 * (SROW * 2) + ks * 32);
        #pragma unroll
        for (int q = 0; q < 4; q++)
            ldsm4(b[q], baddr + q * 16 * (SROW * 2) + ks * 32);
        #pragma unroll
        for (int mf = 0; mf < 2; mf++)
            #pragma unroll
            for (int nf = 0; nf < 8; nf++)
                mma16816(acc[mf][nf], a[mf], b[nf >> 1][(nf & 1) * 2],
                         b[nf >> 1][(nf & 1) * 2 + 1]);
    }

    // Column labels owned by this thread: cols warp_n*64 + nf*8 + 2*(lane&3)+{0,1}
    int lj[8][2];
    #pragma unroll
    for (int nf = 0; nf < 8; nf++) {
        int j = warp_n * 64 + nf * 8 + ((lane & 3) << 1);
        lj[nf][0] = labJ[j];
        lj[nf][1] = labJ[j + 1];
    }

    // Epilogue: 4 rows per thread (mf x rh). D frag: d[2*rh+c] = row t/4+8rh, col 2(t%4)+c.
    int jt = blockIdx.x * 2 + warp_n;
    #pragma unroll
    for (int mf = 0; mf < 2; mf++) {
        #pragma unroll
        for (int rh = 0; rh < 2; rh++) {
            int grow = i0 + warp_m * 32 + mf * 16 + (lane >> 2) + rh * 8;
            int li = lab[grow];
            float neg = 0.0f, pos = 0.0f;
            #pragma unroll
            for (int nf = 0; nf < 8; nf++) {
                float s0 = ex2f(acc[mf][nf][2 * rh]     * EXSCALE);
                float s1 = ex2f(acc[mf][nf][2 * rh + 1] * EXSCALE);
                neg += s0 + s1;
                if (li == lj[nf][0]) pos += s0;
                if (li == lj[nf][1]) pos += s1;
            }
            neg += __shfl_xor_sync(0xffffffffu, neg, 1);
            neg += __shfl_xor_sync(0xffffffffu, neg, 2);
            pos += __shfl_xor_sync(0xffffffffu, pos, 1);
            pos += __shfl_xor_sync(0xffffffffu, pos, 2);
            if ((lane & 3) == 0) {
                g_negp[(size_t)jt * N_ROWS + grow] = neg;
                g_posp[(size_t)jt * N_ROWS + grow] = pos;
            }
        }
    }
}

// Per-row loss: 64 blocks x 256 threads, 2 threads per row (NT/2 each).
__global__ void k_row(const int* __restrict__ lab) {
    int tid = threadIdx.x;
    int r = tid & 127, half = tid >> 7;
    int row = blockIdx.x * 128 + r;
    float neg = 0.f, pos = 0.f;
    #pragma unroll 8
    for (int jt = half * (NT / 2); jt < (half + 1) * (NT / 2); jt++) {
        neg += g_negp[(size_t)jt * N_ROWS + row];
        pos += g_posp[(size_t)jt * N_ROWS + row];
    }
    __shared__ float sn[128], sp[128];
    if (half) { sn[r] = neg; sp[r] = pos; }
    __syncthreads();
    float l = 0.f;
    if (!half) {
        neg += sn[r]; pos += sp[r];
        float self = ex2f(EXSCALE);   // exp(1/T): diagonal term
        int cnt = g_cnt[lab[row] & (NCLS - 1)] - 1;
        l = logf(neg - self) - logf((pos - self) / (float)cnt);
    }
    #pragma unroll
    for (int o = 16; o > 0; o >>= 1) l += __shfl_xor_sync(0xffffffffu, l, o);
    __shared__ float ws[8];
    if ((tid & 31) == 0) ws[tid >> 5] = l;
    __syncthreads();
    if (tid == 0) {
        float s = 0.f;
        #pragma unroll
        for (int i = 0; i < 8; i++) s += ws[i];
        g_bsum[blockIdx.x] = s;
    }
}

__global__ void k_fin(float* __restrict__ out) {
    int t = threadIdx.x;          // 64 threads
    float v = g_bsum[t];
    #pragma unroll
    for (int o = 16; o > 0; o >>= 1) v += __shfl_xor_sync(0xffffffffu, v, o);
    __shared__ float s2[2];
    if ((t & 31) == 0) s2[t >> 5] = v;
    __syncthreads();
    if (t == 0) out[0] = (s2[0] + s2[1]) / (float)N_ROWS;
}

extern "C" void kernel_launch(void* const* d_in, const int* in_sizes, int n_in,
                              void* d_out, int out_size) {
    const float* x   = (const float*)d_in[0];
    const int*   lab = (const int*)d_in[1];
    if (n_in >= 2 && in_sizes[0] < in_sizes[1]) {
        x   = (const float*)d_in[1];
        lab = (const int*)d_in[0];
    }
    float* out = (float*)d_out;

    size_t smem = (size_t)2 * TI * SROW * sizeof(__nv_bfloat16) + TI * sizeof(int);
    cudaFuncSetAttribute(k_pair, cudaFuncAttributeMaxDynamicSharedMemorySize, (int)smem);

    k_init<<<1, 64>>>();
    k_norm<<<N_ROWS, 128>>>(x, lab);
    dim3 grid(NBI, NBI);
    k_pair<<<grid, 256, smem>>>(lab);
    k_row<<<64, 256>>>(lab);
    k_fin<<<1, 64>>>(out);
}

// round 9
// speedup vs baseline: 7.2552x; 1.8656x over previous
#include <cuda_runtime.h>
#include <cuda_bf16.h>
#include <cstdint>

#define N_ROWS 8192
#define DIM    128
#define NCLS   64
#define TI     128                 // CTA tile (M = N = 128)
#define NBI    (N_ROWS / TI)       // 64
#define NT     (NBI * 2)           // 128 partial slots per row
#define NTILES (NBI * (NBI + 1) / 2)   // 2080 upper-tri tiles
#define SROW   136                 // padded smem row stride (bf16 elems) = 272 B

// ---- scratch (__device__ globals; no cudaMalloc allowed) ----
__device__ __nv_bfloat16 g_xb[N_ROWS * DIM];       // normalized rows, bf16
__device__ float g_negp[(size_t)N_ROWS * NT];      // [row][slot]
__device__ float g_posp[(size_t)N_ROWS * NT];
__device__ int   g_cnt[NCLS];
__device__ float g_bsum[256];

#define EXSCALE 2.8853900817779268f   // log2(e)/T, T=0.5

__device__ __forceinline__ uint32_t smem_u32(const void* p) {
    uint32_t a;
    asm("{ .reg .u64 t; cvta.to.shared.u64 t, %1; cvt.u32.u64 %0, t; }" : "=r"(a) : "l"(p));
    return a;
}
__device__ __forceinline__ float ex2f(float x) {
    float r; asm("ex2.approx.f32 %0, %1;" : "=f"(r) : "f"(x)); return r;
}
__device__ __forceinline__ void ldsm4(uint32_t* r, uint32_t addr) {
    asm volatile("ldmatrix.sync.aligned.m8n8.x4.shared.b16 {%0,%1,%2,%3}, [%4];"
                 : "=r"(r[0]), "=r"(r[1]), "=r"(r[2]), "=r"(r[3]) : "r"(addr));
}
__device__ __forceinline__ void mma16816(float* d, const uint32_t* a,
                                         uint32_t b0, uint32_t b1) {
    asm volatile(
        "mma.sync.aligned.m16n8k16.row.col.f32.bf16.bf16.f32 "
        "{%0,%1,%2,%3}, {%4,%5,%6,%7}, {%8,%9}, {%0,%1,%2,%3};"
        : "+f"(d[0]), "+f"(d[1]), "+f"(d[2]), "+f"(d[3])
        : "r"(a[0]), "r"(a[1]), "r"(a[2]), "r"(a[3]), "r"(b0), "r"(b1));
}

__global__ void k_init() {
    if (threadIdx.x < NCLS) g_cnt[threadIdx.x] = 0;
}

__global__ void k_norm(const float* __restrict__ x,
                       const int* __restrict__ lab) {
    int row = blockIdx.x, t = threadIdx.x;
    float v = x[row * DIM + t];
    float ss = v * v;
    #pragma unroll
    for (int o = 16; o > 0; o >>= 1) ss += __shfl_xor_sync(0xffffffffu, ss, o);
    __shared__ float ws[4];
    if ((t & 31) == 0) ws[t >> 5] = ss;
    __syncthreads();
    float nrm = fmaxf(sqrtf(ws[0] + ws[1] + ws[2] + ws[3]), 1e-12f);
    g_xb[row * DIM + t] = __float2bfloat16(v / nrm);
    if (t == 0) atomicAdd(&g_cnt[lab[row] & (NCLS - 1)], 1);
}

// Upper-triangular 128x128 Gram tile (bi <= bj). Row-side partials for tile
// bi rows (slots 2*bj+half) AND column-side partials for tile bj rows
// (slots 2*bi, 2*bi+1) from the same exp values. Deterministic unique writers.
__global__ void __launch_bounds__(256, 2)
k_pair(const int* __restrict__ lab) {
    extern __shared__ char sm[];
    __nv_bfloat16* As = (__nv_bfloat16*)sm;            // [128][SROW]
    __nv_bfloat16* Bs = As + TI * SROW;                // [128][SROW]
    int* labJ = (int*)(Bs + TI * SROW);                // [128]
    float* scol = (float*)sm;                          // reused post-MMA: [2][4][128]

    int tid  = threadIdx.x;
    int w    = tid >> 5;
    int lane = tid & 31;

    // 1D triangular mapping: t = bj*(bj+1)/2 + bi, bi <= bj.
    int t4 = blockIdx.x;
    int bj = (int)((sqrt(8.0 * (double)t4 + 1.0) - 1.0) * 0.5);
    int bi = t4 - bj * (bj + 1) / 2;
    int i0 = bi * TI;
    int j0 = bj * TI;

    // Cooperative tile load.
    #pragma unroll
    for (int it = 0; it < 16; it++) {
        int idx = tid + it * 256;           // 0..4095
        int sub = idx >> 11;                // 0 = A(i), 1 = B(j)
        int loc = idx & 2047;
        int row = loc >> 4, c = loc & 15;
        int grow = (sub ? j0 : i0) + row;
        uint4 v = *(const uint4*)((const char*)g_xb + ((size_t)grow * DIM + c * 8) * 2);
        __nv_bfloat16* dst = sub ? Bs : As;
        *(uint4*)((char*)dst + row * (SROW * 2) + c * 16) = v;
    }
    if (tid < TI) labJ[tid] = lab[j0 + tid];
    __syncthreads();

    int warp_m = w >> 1;                    // 0..3  -> 32-row slab
    int warp_n = w & 1;                     // 0..1  -> 64-col half
    uint32_t asb = smem_u32(As), bsb = smem_u32(Bs);

    uint32_t a_row = (uint32_t)(warp_m * 32 + (lane & 7) + ((lane >> 3) & 1) * 8);
    uint32_t a_k   = (uint32_t)((lane >> 4) * 8);
    uint32_t aaddr = asb + a_row * (SROW * 2) + a_k * 2;
    uint32_t b_n = (uint32_t)(warp_n * 64 + ((lane >> 4) << 3) + (lane & 7));
    uint32_t b_k = (uint32_t)(((lane >> 3) & 1) * 8);
    uint32_t baddr = bsb + b_n * (SROW * 2) + b_k * 2;

    float acc[2][8][4];
    #pragma unroll
    for (int mf = 0; mf < 2; mf++)
        #pragma unroll
        for (int nf = 0; nf < 8; nf++)
            #pragma unroll
            for (int e = 0; e < 4; e++) acc[mf][nf][e] = 0.0f;

    #pragma unroll
    for (int ks = 0; ks < 8; ks++) {
        uint32_t a[2][4], b[4][4];
        ldsm4(a[0], aaddr + ks * 32);
        ldsm4(a[1], aaddr + 16 * (SROW * 2) + ks * 32);
        #pragma unroll
        for (int q = 0; q < 4; q++)
            ldsm4(b[q], baddr + q * 16 * (SROW * 2) + ks * 32);
        #pragma unroll
        for (int mf = 0; mf < 2; mf++)
            #pragma unroll
            for (int nf = 0; nf < 8; nf++)
                mma16816(acc[mf][nf], a[mf], b[nf >> 1][(nf & 1) * 2],
                         b[nf >> 1][(nf & 1) * 2 + 1]);
    }
    __syncthreads();   // done with As/Bs smem; will reuse for scol

    int lj[8][2];
    #pragma unroll
    for (int nf = 0; nf < 8; nf++) {
        int j = warp_n * 64 + nf * 8 + ((lane & 3) << 1);
        lj[nf][0] = labJ[j];
        lj[nf][1] = labJ[j + 1];
    }

    float colneg[8][2], colpos[8][2];
    #pragma unroll
    for (int nf = 0; nf < 8; nf++)
        colneg[nf][0] = colneg[nf][1] = colpos[nf][0] = colpos[nf][1] = 0.0f;

    #pragma unroll
    for (int mf = 0; mf < 2; mf++) {
        #pragma unroll
        for (int rh = 0; rh < 2; rh++) {
            int grow = i0 + warp_m * 32 + mf * 16 + (lane >> 2) + rh * 8;
            int li = lab[grow];
            float neg = 0.0f, pos = 0.0f;
            #pragma unroll
            for (int nf = 0; nf < 8; nf++) {
                float s0 = ex2f(acc[mf][nf][2 * rh]     * EXSCALE);
                float s1 = ex2f(acc[mf][nf][2 * rh + 1] * EXSCALE);
                neg += s0 + s1;
                colneg[nf][0] += s0;
                colneg[nf][1] += s1;
                if (li == lj[nf][0]) { pos += s0; colpos[nf][0] += s0; }
                if (li == lj[nf][1]) { pos += s1; colpos[nf][1] += s1; }
            }
            neg += __shfl_xor_sync(0xffffffffu, neg, 1);
            neg += __shfl_xor_sync(0xffffffffu, neg, 2);
            pos += __shfl_xor_sync(0xffffffffu, pos, 1);
            pos += __shfl_xor_sync(0xffffffffu, pos, 2);
            if ((lane & 3) == 0) {
                g_negp[(size_t)grow * NT + 2 * bj + warp_n] = neg;
                g_posp[(size_t)grow * NT + 2 * bj + warp_n] = pos;
            }
        }
    }

    // Column-side reduce over the 8 row-lanes (lane>>2 groups).
    #pragma unroll
    for (int nf = 0; nf < 8; nf++) {
        #pragma unroll
        for (int c = 0; c < 2; c++) {
            #pragma unroll
            for (int o = 4; o < 32; o <<= 1) {
                colneg[nf][c] += __shfl_xor_sync(0xffffffffu, colneg[nf][c], o);
                colpos[nf][c] += __shfl_xor_sync(0xffffffffu, colpos[nf][c], o);
            }
        }
    }
    if (lane < 4) {
        #pragma unroll
        for (int nf = 0; nf < 8; nf++) {
            int col = warp_n * 64 + nf * 8 + 2 * lane;
            scol[warp_m * 128 + col]           = colneg[nf][0];
            scol[warp_m * 128 + col + 1]       = colneg[nf][1];
            scol[512 + warp_m * 128 + col]     = colpos[nf][0];
            scol[512 + warp_m * 128 + col + 1] = colpos[nf][1];
        }
    }
    __syncthreads();

    if (bi != bj) {
        int col = tid & 127, arr = tid >> 7;   // 0 = neg, 1 = pos
        const float* s = scol + arr * 512;
        float v01 = s[0 * 128 + col] + s[1 * 128 + col];
        float v23 = s[2 * 128 + col] + s[3 * 128 + col];
        float* g = arr ? g_posp : g_negp;
        g[(size_t)(j0 + col) * NT + 2 * bi]     = v01;
        g[(size_t)(j0 + col) * NT + 2 * bi + 1] = v23;
    }
}

// Per-row loss: 65536 threads; 8 threads/row, float4 loads over [row][slot].
__global__ void k_row(const int* __restrict__ lab) {
    int g = blockIdx.x * 256 + threadIdx.x;
    int row = g >> 3, sub = g & 7;
    const float4* np = (const float4*)&g_negp[(size_t)row * NT + sub * 16];
    const float4* pp = (const float4*)&g_posp[(size_t)row * NT + sub * 16];
    float neg = 0.f, pos = 0.f;
    #pragma unroll
    for (int q = 0; q < 4; q++) {
        float4 a = np[q], b = pp[q];
        neg += (a.x + a.y) + (a.z + a.w);
        pos += (b.x + b.y) + (b.z + b.w);
    }
    #pragma unroll
    for (int o = 1; o < 8; o <<= 1) {
        neg += __shfl_xor_sync(0xffffffffu, neg, o);
        pos += __shfl_xor_sync(0xffffffffu, pos, o);
    }
    __shared__ float sl[32];
    if (sub == 0) {
        float self = ex2f(EXSCALE);   // exp(1/T): diagonal term
        int cnt = g_cnt[lab[row] & (NCLS - 1)] - 1;
        sl[(threadIdx.x >> 3)] = logf(neg - self) - logf((pos - self) / (float)cnt);
    }
    __syncthreads();
    if (threadIdx.x < 32) {
        float l = sl[threadIdx.x];
        #pragma unroll
        for (int o = 16; o > 0; o >>= 1) l += __shfl_xor_sync(0xffffffffu, l, o);
        if (threadIdx.x == 0) g_bsum[blockIdx.x] = l;
    }
}

__global__ void k_fin(float* __restrict__ out) {
    int t = threadIdx.x;          // 256 threads
    float v = g_bsum[t];
    #pragma unroll
    for (int o = 16; o > 0; o >>= 1) v += __shfl_xor_sync(0xffffffffu, v, o);
    __shared__ float s2[8];
    if ((t & 31) == 0) s2[t >> 5] = v;
    __syncthreads();
    if (t == 0) {
        float s = 0.f;
        #pragma unroll
        for (int i = 0; i < 8; i++) s += s2[i];
        out[0] = s / (float)N_ROWS;
    }
}

extern "C" void kernel_launch(void* const* d_in, const int* in_sizes, int n_in,
                              void* d_out, int out_size) {
    const float* x   = (const float*)d_in[0];
    const int*   lab = (const int*)d_in[1];
    if (n_in >= 2 && in_sizes[0] < in_sizes[1]) {
        x   = (const float*)d_in[1];
        lab = (const int*)d_in[0];
    }
    float* out = (float*)d_out;

    size_t smem = (size_t)2 * TI * SROW * sizeof(__nv_bfloat16) + TI * sizeof(int);
    cudaFuncSetAttribute(k_pair, cudaFuncAttributeMaxDynamicSharedMemorySize, (int)smem);

    k_init<<<1, 64>>>();
    k_norm<<<N_ROWS, 128>>>(x, lab);
    k_pair<<<NTILES, 256, smem>>>(lab);
    k_row<<<256, 256>>>(lab);
    k_fin<<<1, 256>>>(out);
}